// round 2
// baseline (speedup 1.0000x reference)
#include <cuda_runtime.h>
#include <cuda_bf16.h>
#include <math.h>

// DRR raycast: out[v*W+u] = step(u,v) * sum_s trilinear(volume, p0 + ts*d)
// Inputs (metadata order): volume[256^3] f32, k_inv[1,3,3], rt_inv[1,4,4],
//                          sdd[1], affine_inv[4,4], n_samples int32
// Output: f32 [1,200,200]

#define DRR_W 200
#define DRR_H 200
#define DRR_VOL 256

__device__ __forceinline__ float fetch_vox(const float* __restrict__ vol,
                                           int x, int y, int z) {
    if ((unsigned)x < (unsigned)DRR_VOL &&
        (unsigned)y < (unsigned)DRR_VOL &&
        (unsigned)z < (unsigned)DRR_VOL) {
        return __ldg(vol + (x << 16) + (y << 8) + z);
    }
    return 0.0f;
}

__device__ __forceinline__ float trilinear_guarded(const float* __restrict__ vol,
                                                   float x, float y, float z) {
    float fx = floorf(x), fy = floorf(y), fz = floorf(z);
    int ix = (int)fx, iy = (int)fy, iz = (int)fz;
    float ax = x - fx, ay = y - fy, az = z - fz;

    float c000 = fetch_vox(vol, ix,     iy,     iz);
    float c001 = fetch_vox(vol, ix,     iy,     iz + 1);
    float c010 = fetch_vox(vol, ix,     iy + 1, iz);
    float c011 = fetch_vox(vol, ix,     iy + 1, iz + 1);
    float c100 = fetch_vox(vol, ix + 1, iy,     iz);
    float c101 = fetch_vox(vol, ix + 1, iy,     iz + 1);
    float c110 = fetch_vox(vol, ix + 1, iy + 1, iz);
    float c111 = fetch_vox(vol, ix + 1, iy + 1, iz + 1);

    float c00 = fmaf(az, c001 - c000, c000);
    float c01 = fmaf(az, c011 - c010, c010);
    float c10 = fmaf(az, c101 - c100, c100);
    float c11 = fmaf(az, c111 - c110, c110);
    float c0  = fmaf(ay, c01 - c00, c00);
    float c1  = fmaf(ay, c11 - c10, c10);
    return fmaf(ax, c1 - c0, c0);
}

// Unguarded: caller guarantees x,y,z in [0, 255).
__device__ __forceinline__ float trilinear_fast(const float* __restrict__ vol,
                                                float x, float y, float z) {
    int ix = __float2int_rd(x), iy = __float2int_rd(y), iz = __float2int_rd(z);
    float ax = x - (float)ix, ay = y - (float)iy, az = z - (float)iz;

    const float* p = vol + (ix << 16) + (iy << 8) + iz;
    float c000 = __ldg(p);
    float c001 = __ldg(p + 1);
    float c010 = __ldg(p + 256);
    float c011 = __ldg(p + 257);
    float c100 = __ldg(p + 65536);
    float c101 = __ldg(p + 65537);
    float c110 = __ldg(p + 65792);
    float c111 = __ldg(p + 65793);

    float c00 = fmaf(az, c001 - c000, c000);
    float c01 = fmaf(az, c011 - c010, c010);
    float c10 = fmaf(az, c101 - c100, c100);
    float c11 = fmaf(az, c111 - c110, c110);
    float c0  = fmaf(ay, c01 - c00, c00);
    float c1  = fmaf(ay, c11 - c10, c10);
    return fmaf(ax, c1 - c0, c0);
}

// Clip helper: intersect [lo,hi] with { t : p + t*d in [lo_b, hi_b] }.
__device__ __forceinline__ void axis_clip(float p, float d, float lo_b, float hi_b,
                                          float& lo, float& hi) {
    if (fabsf(d) < 1e-12f) {
        if (p < lo_b || p > hi_b) { lo = 1.0f; hi = 0.0f; }
    } else {
        float r  = 1.0f / d;
        float ta = (lo_b - p) * r;
        float tb = (hi_b - p) * r;
        lo = fmaxf(lo, fminf(ta, tb));
        hi = fminf(hi, fmaxf(ta, tb));
    }
}

// One warp per pixel; lanes stride the sample axis (z-dominant ray direction
// => coalesced corner loads). Warp-reduce at the end.
__global__ __launch_bounds__(256, 8)
void drr_kernel(const float* __restrict__ vol,
                const float* __restrict__ k_inv,
                const float* __restrict__ rt_inv,
                const float* __restrict__ sdd_p,
                const float* __restrict__ aff,
                const int*   __restrict__ n_ptr,
                float* __restrict__ out) {
    int gwarp = (blockIdx.x * blockDim.x + threadIdx.x) >> 5;
    int lane  = threadIdx.x & 31;
    if (gwarp >= DRR_W * DRR_H) return;

    int u = gwarp % DRR_W;
    int v = gwarp / DRR_W;

    int   n    = *n_ptr;
    float fn1  = (float)(n - 1);
    float invn = 1.0f / fn1;
    float sdd  = __ldg(sdd_p);
    float fu = (float)u, fv = (float)v;

    // tgt_cam = k_inv @ (u, v, 1) * sdd
    float tc0 = (__ldg(k_inv + 0) * fu + __ldg(k_inv + 1) * fv + __ldg(k_inv + 2)) * sdd;
    float tc1 = (__ldg(k_inv + 3) * fu + __ldg(k_inv + 4) * fv + __ldg(k_inv + 5)) * sdd;
    float tc2 = (__ldg(k_inv + 6) * fu + __ldg(k_inv + 7) * fv + __ldg(k_inv + 8)) * sdd;

    // ray = R @ tgt_cam ; src = t  (rt_inv is 4x4 row-major)
    float ray0 = __ldg(rt_inv + 0) * tc0 + __ldg(rt_inv + 1) * tc1 + __ldg(rt_inv + 2)  * tc2;
    float ray1 = __ldg(rt_inv + 4) * tc0 + __ldg(rt_inv + 5) * tc1 + __ldg(rt_inv + 6)  * tc2;
    float ray2 = __ldg(rt_inv + 8) * tc0 + __ldg(rt_inv + 9) * tc1 + __ldg(rt_inv + 10) * tc2;
    float sx = __ldg(rt_inv + 3), sy = __ldg(rt_inv + 7), sz = __ldg(rt_inv + 11);

    float step = sqrtf(ray0 * ray0 + ray1 * ray1 + ray2 * ray2) * invn;

    // vox(s) = p0 + ts * d   (affine_inv 4x4 row-major; only top 3 rows used)
    float p0x = __ldg(aff + 0) * sx + __ldg(aff + 1) * sy + __ldg(aff + 2)  * sz + __ldg(aff + 3);
    float p0y = __ldg(aff + 4) * sx + __ldg(aff + 5) * sy + __ldg(aff + 6)  * sz + __ldg(aff + 7);
    float p0z = __ldg(aff + 8) * sx + __ldg(aff + 9) * sy + __ldg(aff + 10) * sz + __ldg(aff + 11);
    float dx  = __ldg(aff + 0) * ray0 + __ldg(aff + 1) * ray1 + __ldg(aff + 2)  * ray2;
    float dy  = __ldg(aff + 4) * ray0 + __ldg(aff + 5) * ray1 + __ldg(aff + 6)  * ray2;
    float dz  = __ldg(aff + 8) * ray0 + __ldg(aff + 9) * ray1 + __ldg(aff + 10) * ray2;

    // Outer clip: any nonzero contribution requires coords in [-1, VOL].
    float lo = 0.0f, hi = 1.0f;
    axis_clip(p0x, dx, -1.0f, (float)DRR_VOL, lo, hi);
    axis_clip(p0y, dy, -1.0f, (float)DRR_VOL, lo, hi);
    axis_clip(p0z, dz, -1.0f, (float)DRR_VOL, lo, hi);

    // Interior clip: all 8 corners in-bounds when coords in [0, 254.99].
    float li = 0.0f, hii = 1.0f;
    axis_clip(p0x, dx, 0.0f, 254.99f, li, hii);
    axis_clip(p0y, dy, 0.0f, 254.99f, li, hii);
    axis_clip(p0z, dz, 0.0f, 254.99f, li, hii);

    float acc = 0.0f;
    if (lo <= hi) {
        int s_lo = (int)floorf(lo * fn1) - 2;
        int s_hi = (int)ceilf(hi * fn1) + 2;
        if (s_lo < 0) s_lo = 0;
        if (s_hi > n - 1) s_hi = n - 1;

        // Certified-interior sample range (±1 sample safety margin).
        int si_lo, si_hi;
        if (li <= hii) {
            si_lo = (int)ceilf(li * fn1) + 1;
            si_hi = (int)floorf(hii * fn1) - 1;
        } else {
            si_lo = 1; si_hi = 0;  // empty
        }

        // Per-sample direction scaled by 1/(n-1): coords are pure FMA in s.
        float ddx = dx * invn, ddy = dy * invn, ddz = dz * invn;

        for (int s = s_lo + lane; s <= s_hi; s += 32) {
            float sf = (float)s;
            float x = fmaf(sf, ddx, p0x);
            float y = fmaf(sf, ddy, p0y);
            float z = fmaf(sf, ddz, p0z);
            if (s >= si_lo && s <= si_hi) {
                acc += trilinear_fast(vol, x, y, z);
            } else {
                acc += trilinear_guarded(vol, x, y, z);
            }
        }
    }

    // Warp reduction
    #pragma unroll
    for (int o = 16; o > 0; o >>= 1)
        acc += __shfl_down_sync(0xFFFFFFFFu, acc, o);

    if (lane == 0) out[gwarp] = acc * step;
}

extern "C" void kernel_launch(void* const* d_in, const int* in_sizes, int n_in,
                              void* d_out, int out_size) {
    const float* vol    = (const float*)d_in[0];
    const float* k_inv  = (const float*)d_in[1];
    const float* rt_inv = (const float*)d_in[2];
    const float* sdd    = (const float*)d_in[3];
    const float* aff    = (const float*)d_in[4];
    const int*   n_ptr  = (const int*)d_in[5];
    float* out = (float*)d_out;

    int n_warps = DRR_W * DRR_H;            // one warp per pixel
    int threads = 256;                      // 8 warps per block
    int blocks  = (n_warps * 32 + threads - 1) / threads;
    drr_kernel<<<blocks, threads>>>(vol, k_inv, rt_inv, sdd, aff, n_ptr, out);
}

// round 4
// speedup vs baseline: 1.1056x; 1.1056x over previous
#include <cuda_runtime.h>
#include <cuda_bf16.h>
#include <math.h>

// DRR raycast: out[v*W+u] = step(u,v) * sum_s trilinear(volume, p0 + ts*d)
// Inputs (metadata order): volume[256^3] f32, k_inv[1,3,3], rt_inv[1,4,4],
//                          sdd[1], affine_inv[4,4], n_samples int32
// Output: f32 [1,200,200]

#define DRR_W 200
#define DRR_H 200
#define DRR_VOL 256

__device__ __forceinline__ float fetch_vox(const float* __restrict__ vol,
                                           int x, int y, int z) {
    if ((unsigned)x < (unsigned)DRR_VOL &&
        (unsigned)y < (unsigned)DRR_VOL &&
        (unsigned)z < (unsigned)DRR_VOL) {
        return __ldg(vol + (x << 16) + (y << 8) + z);
    }
    return 0.0f;
}

// Guarded trilinear (boundary samples): guards compile to predicated LDGs.
__device__ __forceinline__ float trilinear_guarded(const float* __restrict__ vol,
                                                   float x, float y, float z) {
    float fx = floorf(x), fy = floorf(y), fz = floorf(z);
    int ix = (int)fx, iy = (int)fy, iz = (int)fz;
    float ax = x - fx, ay = y - fy, az = z - fz;

    float c000 = fetch_vox(vol, ix,     iy,     iz);
    float c001 = fetch_vox(vol, ix,     iy,     iz + 1);
    float c010 = fetch_vox(vol, ix,     iy + 1, iz);
    float c011 = fetch_vox(vol, ix,     iy + 1, iz + 1);
    float c100 = fetch_vox(vol, ix + 1, iy,     iz);
    float c101 = fetch_vox(vol, ix + 1, iy,     iz + 1);
    float c110 = fetch_vox(vol, ix + 1, iy + 1, iz);
    float c111 = fetch_vox(vol, ix + 1, iy + 1, iz + 1);

    float c00 = fmaf(az, c001 - c000, c000);
    float c01 = fmaf(az, c011 - c010, c010);
    float c10 = fmaf(az, c101 - c100, c100);
    float c11 = fmaf(az, c111 - c110, c110);
    float c0  = fmaf(ay, c01 - c00, c00);
    float c1  = fmaf(ay, c11 - c10, c10);
    return fmaf(ax, c1 - c0, c0);
}

// Clip helper: intersect [lo,hi] with { t : p + t*d in [lo_b, hi_b] }.
__device__ __forceinline__ void axis_clip(float p, float d, float lo_b, float hi_b,
                                          float& lo, float& hi) {
    if (fabsf(d) < 1e-12f) {
        if (p < lo_b || p > hi_b) { lo = 1.0f; hi = 0.0f; }
    } else {
        float r  = 1.0f / d;
        float ta = (lo_b - p) * r;
        float tb = (hi_b - p) * r;
        lo = fmaxf(lo, fminf(ta, tb));
        hi = fminf(hi, fmaxf(ta, tb));
    }
}

// One warp per pixel; lanes stride the sample axis (z-dominant ray direction
// => coalesced corner loads). Three sequential loops: guarded head, unguarded
// interior bulk, guarded tail. No branches inside loop bodies.
__global__ __launch_bounds__(256, 8)
void drr_kernel(const float* __restrict__ vol,
                const float* __restrict__ k_inv,
                const float* __restrict__ rt_inv,
                const float* __restrict__ sdd_p,
                const float* __restrict__ aff,
                const int*   __restrict__ n_ptr,
                float* __restrict__ out) {
    int gwarp = (blockIdx.x * blockDim.x + threadIdx.x) >> 5;
    int lane  = threadIdx.x & 31;
    if (gwarp >= DRR_W * DRR_H) return;

    int u = gwarp % DRR_W;
    int v = gwarp / DRR_W;

    int   n    = *n_ptr;
    float fn1  = (float)(n - 1);
    float invn = 1.0f / fn1;
    float sdd  = __ldg(sdd_p);
    float fu = (float)u, fv = (float)v;

    // tgt_cam = k_inv @ (u, v, 1) * sdd
    float tc0 = (__ldg(k_inv + 0) * fu + __ldg(k_inv + 1) * fv + __ldg(k_inv + 2)) * sdd;
    float tc1 = (__ldg(k_inv + 3) * fu + __ldg(k_inv + 4) * fv + __ldg(k_inv + 5)) * sdd;
    float tc2 = (__ldg(k_inv + 6) * fu + __ldg(k_inv + 7) * fv + __ldg(k_inv + 8)) * sdd;

    // ray = R @ tgt_cam ; src = t  (rt_inv is 4x4 row-major)
    float ray0 = __ldg(rt_inv + 0) * tc0 + __ldg(rt_inv + 1) * tc1 + __ldg(rt_inv + 2)  * tc2;
    float ray1 = __ldg(rt_inv + 4) * tc0 + __ldg(rt_inv + 5) * tc1 + __ldg(rt_inv + 6)  * tc2;
    float ray2 = __ldg(rt_inv + 8) * tc0 + __ldg(rt_inv + 9) * tc1 + __ldg(rt_inv + 10) * tc2;
    float sx = __ldg(rt_inv + 3), sy = __ldg(rt_inv + 7), sz = __ldg(rt_inv + 11);

    float step = sqrtf(ray0 * ray0 + ray1 * ray1 + ray2 * ray2) * invn;

    // vox(s) = p0 + ts * d   (affine_inv 4x4 row-major; only top 3 rows used)
    float p0x = __ldg(aff + 0) * sx + __ldg(aff + 1) * sy + __ldg(aff + 2)  * sz + __ldg(aff + 3);
    float p0y = __ldg(aff + 4) * sx + __ldg(aff + 5) * sy + __ldg(aff + 6)  * sz + __ldg(aff + 7);
    float p0z = __ldg(aff + 8) * sx + __ldg(aff + 9) * sy + __ldg(aff + 10) * sz + __ldg(aff + 11);
    float dx  = __ldg(aff + 0) * ray0 + __ldg(aff + 1) * ray1 + __ldg(aff + 2)  * ray2;
    float dy  = __ldg(aff + 4) * ray0 + __ldg(aff + 5) * ray1 + __ldg(aff + 6)  * ray2;
    float dz  = __ldg(aff + 8) * ray0 + __ldg(aff + 9) * ray1 + __ldg(aff + 10) * ray2;

    // Outer clip: any nonzero contribution requires coords in [-1, VOL].
    float lo = 0.0f, hi = 1.0f;
    axis_clip(p0x, dx, -1.0f, (float)DRR_VOL, lo, hi);
    axis_clip(p0y, dy, -1.0f, (float)DRR_VOL, lo, hi);
    axis_clip(p0z, dz, -1.0f, (float)DRR_VOL, lo, hi);

    // Interior clip: all 8 corners provably in-bounds when coords in [0, 254.99].
    float li = 0.0f, hii = 1.0f;
    axis_clip(p0x, dx, 0.0f, 254.99f, li, hii);
    axis_clip(p0y, dy, 0.0f, 254.99f, li, hii);
    axis_clip(p0z, dz, 0.0f, 254.99f, li, hii);

    float acc = 0.0f;
    if (lo <= hi) {
        int s_lo = (int)floorf(lo * fn1) - 2;
        int s_hi = (int)ceilf(hi * fn1) + 2;
        if (s_lo < 0) s_lo = 0;
        if (s_hi > n - 1) s_hi = n - 1;

        // Certified-interior range [A, B] within [s_lo, s_hi] (±1 margin).
        int A, B;
        if (li <= hii) {
            A = (int)ceilf(li * fn1) + 1;
            B = (int)floorf(hii * fn1) - 1;
            if (A < s_lo) A = s_lo;
            if (B > s_hi) B = s_hi;
            if (B < A) { A = s_hi + 1; B = s_hi; }   // empty interior
        } else {
            A = s_hi + 1; B = s_hi;                   // empty interior
        }

        // Per-sample direction scaled by 1/(n-1): coords are pure FMA in s.
        float ddx = dx * invn, ddy = dy * invn, ddz = dz * invn;

        // --- Guarded head: [s_lo, A-1] ---
        for (int s = s_lo + lane; s <= A - 1; s += 32) {
            float sf = (float)s;
            acc += trilinear_guarded(vol,
                                     fmaf(sf, ddx, p0x),
                                     fmaf(sf, ddy, p0y),
                                     fmaf(sf, ddz, p0z));
        }

        // --- Unguarded interior bulk: [A, B] ---
        for (int s = A + lane; s <= B; s += 32) {
            float sf = (float)s;
            float x = fmaf(sf, ddx, p0x);
            float y = fmaf(sf, ddy, p0y);
            float z = fmaf(sf, ddz, p0z);
            int ix = __float2int_rd(x), iy = __float2int_rd(y), iz = __float2int_rd(z);
            float ax = x - (float)ix, ay = y - (float)iy, az = z - (float)iz;

            const float* p = vol + (ix << 16) + (iy << 8) + iz;
            float c000 = __ldg(p);
            float c001 = __ldg(p + 1);
            float c010 = __ldg(p + 256);
            float c011 = __ldg(p + 257);
            float c100 = __ldg(p + 65536);
            float c101 = __ldg(p + 65537);
            float c110 = __ldg(p + 65792);
            float c111 = __ldg(p + 65793);

            float c00 = fmaf(az, c001 - c000, c000);
            float c01 = fmaf(az, c011 - c010, c010);
            float c10 = fmaf(az, c101 - c100, c100);
            float c11 = fmaf(az, c111 - c110, c110);
            float c0  = fmaf(ay, c01 - c00, c00);
            float c1  = fmaf(ay, c11 - c10, c10);
            acc += fmaf(ax, c1 - c0, c0);
        }

        // --- Guarded tail: [B+1, s_hi] ---
        for (int s = B + 1 + lane; s <= s_hi; s += 32) {
            float sf = (float)s;
            acc += trilinear_guarded(vol,
                                     fmaf(sf, ddx, p0x),
                                     fmaf(sf, ddy, p0y),
                                     fmaf(sf, ddz, p0z));
        }
    }

    // Warp reduction
    #pragma unroll
    for (int o = 16; o > 0; o >>= 1)
        acc += __shfl_down_sync(0xFFFFFFFFu, acc, o);

    if (lane == 0) out[gwarp] = acc * step;
}

extern "C" void kernel_launch(void* const* d_in, const int* in_sizes, int n_in,
                              void* d_out, int out_size) {
    const float* vol    = (const float*)d_in[0];
    const float* k_inv  = (const float*)d_in[1];
    const float* rt_inv = (const float*)d_in[2];
    const float* sdd    = (const float*)d_in[3];
    const float* aff    = (const float*)d_in[4];
    const int*   n_ptr  = (const int*)d_in[5];
    float* out = (float*)d_out;

    int n_warps = DRR_W * DRR_H;            // one warp per pixel
    int threads = 256;                      // 8 warps per block
    int blocks  = (n_warps * 32 + threads - 1) / threads;
    drr_kernel<<<blocks, threads>>>(vol, k_inv, rt_inv, sdd, aff, n_ptr, out);
}

// round 5
// speedup vs baseline: 1.7130x; 1.5494x over previous
#include <cuda_runtime.h>
#include <cuda_bf16.h>
#include <math.h>

// DRR raycast: out[v*W+u] = step(u,v) * sum_s trilinear(volume, p0 + ts*d)
// Inputs (metadata order): volume[256^3] f32, k_inv[1,3,3], rt_inv[1,4,4],
//                          sdd[1], affine_inv[4,4], n_samples int32
// Output: f32 [1,200,200]

#define DRR_W 200
#define DRR_H 200
#define DRR_VOL 256

__device__ __forceinline__ float fetch_vox(const float* __restrict__ vol,
                                           int x, int y, int z) {
    if ((unsigned)x < (unsigned)DRR_VOL &&
        (unsigned)y < (unsigned)DRR_VOL &&
        (unsigned)z < (unsigned)DRR_VOL) {
        return __ldg(vol + (x << 16) + (y << 8) + z);
    }
    return 0.0f;
}

// Guarded trilinear (boundary samples): guards compile to predicated LDGs.
__device__ __forceinline__ float trilinear_guarded(const float* __restrict__ vol,
                                                   float x, float y, float z) {
    float fx = floorf(x), fy = floorf(y), fz = floorf(z);
    int ix = (int)fx, iy = (int)fy, iz = (int)fz;
    float ax = x - fx, ay = y - fy, az = z - fz;

    float c000 = fetch_vox(vol, ix,     iy,     iz);
    float c001 = fetch_vox(vol, ix,     iy,     iz + 1);
    float c010 = fetch_vox(vol, ix,     iy + 1, iz);
    float c011 = fetch_vox(vol, ix,     iy + 1, iz + 1);
    float c100 = fetch_vox(vol, ix + 1, iy,     iz);
    float c101 = fetch_vox(vol, ix + 1, iy,     iz + 1);
    float c110 = fetch_vox(vol, ix + 1, iy + 1, iz);
    float c111 = fetch_vox(vol, ix + 1, iy + 1, iz + 1);

    float c00 = fmaf(az, c001 - c000, c000);
    float c01 = fmaf(az, c011 - c010, c010);
    float c10 = fmaf(az, c101 - c100, c100);
    float c11 = fmaf(az, c111 - c110, c110);
    float c0  = fmaf(ay, c01 - c00, c00);
    float c1  = fmaf(ay, c11 - c10, c10);
    return fmaf(ax, c1 - c0, c0);
}

// Clip helper: intersect [lo,hi] with { t : p + t*d in [lo_b, hi_b] }.
__device__ __forceinline__ void axis_clip(float p, float d, float lo_b, float hi_b,
                                          float& lo, float& hi) {
    if (fabsf(d) < 1e-12f) {
        if (p < lo_b || p > hi_b) { lo = 1.0f; hi = 0.0f; }
    } else {
        float r  = 1.0f / d;
        float ta = (lo_b - p) * r;
        float tb = (hi_b - p) * r;
        lo = fmaxf(lo, fminf(ta, tb));
        hi = fminf(hi, fmaxf(ta, tb));
    }
}

// One warp per pixel; lanes stride the sample axis (z-dominant ray direction
// => coalesced corner loads). Three sequential loops: guarded head, unguarded
// interior bulk, guarded tail. Register cap relaxed to 64 (occupancy 4 blocks)
// so the interior's 8 concurrent loads stay in registers — no local spills.
__global__ __launch_bounds__(256, 4)
void drr_kernel(const float* __restrict__ vol,
                const float* __restrict__ k_inv,
                const float* __restrict__ rt_inv,
                const float* __restrict__ sdd_p,
                const float* __restrict__ aff,
                const int*   __restrict__ n_ptr,
                float* __restrict__ out) {
    int gwarp = (blockIdx.x * blockDim.x + threadIdx.x) >> 5;
    int lane  = threadIdx.x & 31;
    if (gwarp >= DRR_W * DRR_H) return;

    int u = gwarp % DRR_W;
    int v = gwarp / DRR_W;

    int   n    = *n_ptr;
    float fn1  = (float)(n - 1);
    float invn = 1.0f / fn1;
    float sdd  = __ldg(sdd_p);
    float fu = (float)u, fv = (float)v;

    // tgt_cam = k_inv @ (u, v, 1) * sdd
    float tc0 = (__ldg(k_inv + 0) * fu + __ldg(k_inv + 1) * fv + __ldg(k_inv + 2)) * sdd;
    float tc1 = (__ldg(k_inv + 3) * fu + __ldg(k_inv + 4) * fv + __ldg(k_inv + 5)) * sdd;
    float tc2 = (__ldg(k_inv + 6) * fu + __ldg(k_inv + 7) * fv + __ldg(k_inv + 8)) * sdd;

    // ray = R @ tgt_cam ; src = t  (rt_inv is 4x4 row-major)
    float ray0 = __ldg(rt_inv + 0) * tc0 + __ldg(rt_inv + 1) * tc1 + __ldg(rt_inv + 2)  * tc2;
    float ray1 = __ldg(rt_inv + 4) * tc0 + __ldg(rt_inv + 5) * tc1 + __ldg(rt_inv + 6)  * tc2;
    float ray2 = __ldg(rt_inv + 8) * tc0 + __ldg(rt_inv + 9) * tc1 + __ldg(rt_inv + 10) * tc2;
    float sx = __ldg(rt_inv + 3), sy = __ldg(rt_inv + 7), sz = __ldg(rt_inv + 11);

    float step = sqrtf(ray0 * ray0 + ray1 * ray1 + ray2 * ray2) * invn;

    // vox(s) = p0 + ts * d   (affine_inv 4x4 row-major; only top 3 rows used)
    float p0x = __ldg(aff + 0) * sx + __ldg(aff + 1) * sy + __ldg(aff + 2)  * sz + __ldg(aff + 3);
    float p0y = __ldg(aff + 4) * sx + __ldg(aff + 5) * sy + __ldg(aff + 6)  * sz + __ldg(aff + 7);
    float p0z = __ldg(aff + 8) * sx + __ldg(aff + 9) * sy + __ldg(aff + 10) * sz + __ldg(aff + 11);
    float dx  = __ldg(aff + 0) * ray0 + __ldg(aff + 1) * ray1 + __ldg(aff + 2)  * ray2;
    float dy  = __ldg(aff + 4) * ray0 + __ldg(aff + 5) * ray1 + __ldg(aff + 6)  * ray2;
    float dz  = __ldg(aff + 8) * ray0 + __ldg(aff + 9) * ray1 + __ldg(aff + 10) * ray2;

    // Outer clip: any nonzero contribution requires coords in [-1, VOL].
    float lo = 0.0f, hi = 1.0f;
    axis_clip(p0x, dx, -1.0f, (float)DRR_VOL, lo, hi);
    axis_clip(p0y, dy, -1.0f, (float)DRR_VOL, lo, hi);
    axis_clip(p0z, dz, -1.0f, (float)DRR_VOL, lo, hi);

    // Interior clip: all 8 corners provably in-bounds when coords in [0, 254.99].
    float li = 0.0f, hii = 1.0f;
    axis_clip(p0x, dx, 0.0f, 254.99f, li, hii);
    axis_clip(p0y, dy, 0.0f, 254.99f, li, hii);
    axis_clip(p0z, dz, 0.0f, 254.99f, li, hii);

    float acc = 0.0f;
    if (lo <= hi) {
        int s_lo = (int)floorf(lo * fn1) - 2;
        int s_hi = (int)ceilf(hi * fn1) + 2;
        if (s_lo < 0) s_lo = 0;
        if (s_hi > n - 1) s_hi = n - 1;

        // Certified-interior range [A, B] within [s_lo, s_hi] (±1 margin).
        int A, B;
        if (li <= hii) {
            A = (int)ceilf(li * fn1) + 1;
            B = (int)floorf(hii * fn1) - 1;
            if (A < s_lo) A = s_lo;
            if (B > s_hi) B = s_hi;
            if (B < A) { A = s_hi + 1; B = s_hi; }   // empty interior
        } else {
            A = s_hi + 1; B = s_hi;                   // empty interior
        }

        // Per-sample direction scaled by 1/(n-1): coords are pure FMA in s.
        float ddx = dx * invn, ddy = dy * invn, ddz = dz * invn;

        // --- Guarded head: [s_lo, A-1] ---
        for (int s = s_lo + lane; s <= A - 1; s += 32) {
            float sf = (float)s;
            acc += trilinear_guarded(vol,
                                     fmaf(sf, ddx, p0x),
                                     fmaf(sf, ddy, p0y),
                                     fmaf(sf, ddz, p0z));
        }

        // --- Unguarded interior bulk: [A, B] ---
        for (int s = A + lane; s <= B; s += 32) {
            float sf = (float)s;
            float x = fmaf(sf, ddx, p0x);
            float y = fmaf(sf, ddy, p0y);
            float z = fmaf(sf, ddz, p0z);
            int ix = __float2int_rd(x), iy = __float2int_rd(y), iz = __float2int_rd(z);
            float ax = x - (float)ix, ay = y - (float)iy, az = z - (float)iz;

            const float* p = vol + (ix << 16) + (iy << 8) + iz;
            float c000 = __ldg(p);
            float c001 = __ldg(p + 1);
            float c010 = __ldg(p + 256);
            float c011 = __ldg(p + 257);
            float c100 = __ldg(p + 65536);
            float c101 = __ldg(p + 65537);
            float c110 = __ldg(p + 65792);
            float c111 = __ldg(p + 65793);

            float c00 = fmaf(az, c001 - c000, c000);
            float c01 = fmaf(az, c011 - c010, c010);
            float c10 = fmaf(az, c101 - c100, c100);
            float c11 = fmaf(az, c111 - c110, c110);
            float c0  = fmaf(ay, c01 - c00, c00);
            float c1  = fmaf(ay, c11 - c10, c10);
            acc += fmaf(ax, c1 - c0, c0);
        }

        // --- Guarded tail: [B+1, s_hi] ---
        for (int s = B + 1 + lane; s <= s_hi; s += 32) {
            float sf = (float)s;
            acc += trilinear_guarded(vol,
                                     fmaf(sf, ddx, p0x),
                                     fmaf(sf, ddy, p0y),
                                     fmaf(sf, ddz, p0z));
        }
    }

    // Warp reduction
    #pragma unroll
    for (int o = 16; o > 0; o >>= 1)
        acc += __shfl_down_sync(0xFFFFFFFFu, acc, o);

    if (lane == 0) out[gwarp] = acc * step;
}

extern "C" void kernel_launch(void* const* d_in, const int* in_sizes, int n_in,
                              void* d_out, int out_size) {
    const float* vol    = (const float*)d_in[0];
    const float* k_inv  = (const float*)d_in[1];
    const float* rt_inv = (const float*)d_in[2];
    const float* sdd    = (const float*)d_in[3];
    const float* aff    = (const float*)d_in[4];
    const int*   n_ptr  = (const int*)d_in[5];
    float* out = (float*)d_out;

    int n_warps = DRR_W * DRR_H;            // one warp per pixel
    int threads = 256;                      // 8 warps per block
    int blocks  = (n_warps * 32 + threads - 1) / threads;
    drr_kernel<<<blocks, threads>>>(vol, k_inv, rt_inv, sdd, aff, n_ptr, out);
}

// round 6
// speedup vs baseline: 1.7143x; 1.0008x over previous
#include <cuda_runtime.h>
#include <cuda_bf16.h>
#include <math.h>

// DRR raycast: out[v*W+u] = step(u,v) * sum_s trilinear(volume, p0 + ts*d)
// Inputs (metadata order): volume[256^3] f32, k_inv[1,3,3], rt_inv[1,4,4],
//                          sdd[1], affine_inv[4,4], n_samples int32
// Output: f32 [1,200,200]

#define DRR_W 200
#define DRR_H 200
#define DRR_VOL 256

__device__ __forceinline__ float fetch_vox(const float* __restrict__ vol,
                                           int x, int y, int z) {
    if ((unsigned)x < (unsigned)DRR_VOL &&
        (unsigned)y < (unsigned)DRR_VOL &&
        (unsigned)z < (unsigned)DRR_VOL) {
        return __ldg(vol + (x << 16) + (y << 8) + z);
    }
    return 0.0f;
}

// Guarded trilinear (boundary samples): guards compile to predicated LDGs.
__device__ __forceinline__ float trilinear_guarded(const float* __restrict__ vol,
                                                   float x, float y, float z) {
    float fx = floorf(x), fy = floorf(y), fz = floorf(z);
    int ix = (int)fx, iy = (int)fy, iz = (int)fz;
    float ax = x - fx, ay = y - fy, az = z - fz;

    float c000 = fetch_vox(vol, ix,     iy,     iz);
    float c001 = fetch_vox(vol, ix,     iy,     iz + 1);
    float c010 = fetch_vox(vol, ix,     iy + 1, iz);
    float c011 = fetch_vox(vol, ix,     iy + 1, iz + 1);
    float c100 = fetch_vox(vol, ix + 1, iy,     iz);
    float c101 = fetch_vox(vol, ix + 1, iy,     iz + 1);
    float c110 = fetch_vox(vol, ix + 1, iy + 1, iz);
    float c111 = fetch_vox(vol, ix + 1, iy + 1, iz + 1);

    float c00 = fmaf(az, c001 - c000, c000);
    float c01 = fmaf(az, c011 - c010, c010);
    float c10 = fmaf(az, c101 - c100, c100);
    float c11 = fmaf(az, c111 - c110, c110);
    float c0  = fmaf(ay, c01 - c00, c00);
    float c1  = fmaf(ay, c11 - c10, c10);
    return fmaf(ax, c1 - c0, c0);
}

// Clip helper: intersect [lo,hi] with { t : p + t*d in [lo_b, hi_b] }.
__device__ __forceinline__ void axis_clip(float p, float d, float lo_b, float hi_b,
                                          float& lo, float& hi) {
    if (fabsf(d) < 1e-12f) {
        if (p < lo_b || p > hi_b) { lo = 1.0f; hi = 0.0f; }
    } else {
        float r  = 1.0f / d;
        float ta = (lo_b - p) * r;
        float tb = (hi_b - p) * r;
        lo = fmaxf(lo, fminf(ta, tb));
        hi = fminf(hi, fmaxf(ta, tb));
    }
}

// One warp per pixel; lanes stride the sample axis (z-dominant ray direction
// => coalesced corner loads). Guarded head / unguarded interior / guarded tail.
// launch_bounds(256,6): regs capped ~42 -> 48 warps/SM (75% occ) for L1 sharing
// across neighboring rays, while keeping the cheap unguarded interior.
__global__ __launch_bounds__(256, 6)
void drr_kernel(const float* __restrict__ vol,
                const float* __restrict__ k_inv,
                const float* __restrict__ rt_inv,
                const float* __restrict__ sdd_p,
                const float* __restrict__ aff,
                const int*   __restrict__ n_ptr,
                float* __restrict__ out) {
    int gwarp = (blockIdx.x * blockDim.x + threadIdx.x) >> 5;
    int lane  = threadIdx.x & 31;
    if (gwarp >= DRR_W * DRR_H) return;

    int u = gwarp % DRR_W;
    int v = gwarp / DRR_W;

    int   n    = *n_ptr;
    float fn1  = (float)(n - 1);
    float invn = 1.0f / fn1;
    float sdd  = __ldg(sdd_p);
    float fu = (float)u, fv = (float)v;

    // tgt_cam = k_inv @ (u, v, 1) * sdd
    float tc0 = (__ldg(k_inv + 0) * fu + __ldg(k_inv + 1) * fv + __ldg(k_inv + 2)) * sdd;
    float tc1 = (__ldg(k_inv + 3) * fu + __ldg(k_inv + 4) * fv + __ldg(k_inv + 5)) * sdd;
    float tc2 = (__ldg(k_inv + 6) * fu + __ldg(k_inv + 7) * fv + __ldg(k_inv + 8)) * sdd;

    // ray = R @ tgt_cam ; src = t  (rt_inv is 4x4 row-major)
    float ray0 = __ldg(rt_inv + 0) * tc0 + __ldg(rt_inv + 1) * tc1 + __ldg(rt_inv + 2)  * tc2;
    float ray1 = __ldg(rt_inv + 4) * tc0 + __ldg(rt_inv + 5) * tc1 + __ldg(rt_inv + 6)  * tc2;
    float ray2 = __ldg(rt_inv + 8) * tc0 + __ldg(rt_inv + 9) * tc1 + __ldg(rt_inv + 10) * tc2;
    float sx = __ldg(rt_inv + 3), sy = __ldg(rt_inv + 7), sz = __ldg(rt_inv + 11);

    float step = sqrtf(ray0 * ray0 + ray1 * ray1 + ray2 * ray2) * invn;

    // vox(s) = p0 + ts * d   (affine_inv 4x4 row-major; only top 3 rows used)
    float p0x = __ldg(aff + 0) * sx + __ldg(aff + 1) * sy + __ldg(aff + 2)  * sz + __ldg(aff + 3);
    float p0y = __ldg(aff + 4) * sx + __ldg(aff + 5) * sy + __ldg(aff + 6)  * sz + __ldg(aff + 7);
    float p0z = __ldg(aff + 8) * sx + __ldg(aff + 9) * sy + __ldg(aff + 10) * sz + __ldg(aff + 11);
    float dx  = __ldg(aff + 0) * ray0 + __ldg(aff + 1) * ray1 + __ldg(aff + 2)  * ray2;
    float dy  = __ldg(aff + 4) * ray0 + __ldg(aff + 5) * ray1 + __ldg(aff + 6)  * ray2;
    float dz  = __ldg(aff + 8) * ray0 + __ldg(aff + 9) * ray1 + __ldg(aff + 10) * ray2;

    // Outer clip: any nonzero contribution requires coords in [-1, VOL].
    float lo = 0.0f, hi = 1.0f;
    axis_clip(p0x, dx, -1.0f, (float)DRR_VOL, lo, hi);
    axis_clip(p0y, dy, -1.0f, (float)DRR_VOL, lo, hi);
    axis_clip(p0z, dz, -1.0f, (float)DRR_VOL, lo, hi);

    // Interior clip: all 8 corners provably in-bounds when coords in [0, 254.99].
    float li = 0.0f, hii = 1.0f;
    axis_clip(p0x, dx, 0.0f, 254.99f, li, hii);
    axis_clip(p0y, dy, 0.0f, 254.99f, li, hii);
    axis_clip(p0z, dz, 0.0f, 254.99f, li, hii);

    float acc = 0.0f;
    if (lo <= hi) {
        int s_lo = (int)floorf(lo * fn1) - 2;
        int s_hi = (int)ceilf(hi * fn1) + 2;
        if (s_lo < 0) s_lo = 0;
        if (s_hi > n - 1) s_hi = n - 1;

        // Certified-interior range [A, B] within [s_lo, s_hi] (±1 margin).
        int A, B;
        if (li <= hii) {
            A = (int)ceilf(li * fn1) + 1;
            B = (int)floorf(hii * fn1) - 1;
            if (A < s_lo) A = s_lo;
            if (B > s_hi) B = s_hi;
            if (B < A) { A = s_hi + 1; B = s_hi; }   // empty interior
        } else {
            A = s_hi + 1; B = s_hi;                   // empty interior
        }

        // Per-sample direction scaled by 1/(n-1): coords are pure FMA in s.
        float ddx = dx * invn, ddy = dy * invn, ddz = dz * invn;

        // --- Guarded head: [s_lo, A-1] (at most ~1 iteration per lane) ---
        #pragma unroll 1
        for (int s = s_lo + lane; s <= A - 1; s += 32) {
            float sf = (float)s;
            acc += trilinear_guarded(vol,
                                     fmaf(sf, ddx, p0x),
                                     fmaf(sf, ddy, p0y),
                                     fmaf(sf, ddz, p0z));
        }

        // --- Unguarded interior bulk: [A, B] ---
        #pragma unroll 1
        for (int s = A + lane; s <= B; s += 32) {
            float sf = (float)s;
            float x = fmaf(sf, ddx, p0x);
            float y = fmaf(sf, ddy, p0y);
            float z = fmaf(sf, ddz, p0z);
            int ix = __float2int_rd(x), iy = __float2int_rd(y), iz = __float2int_rd(z);
            float ax = x - (float)ix, ay = y - (float)iy, az = z - (float)iz;

            const float* p = vol + (ix << 16) + (iy << 8) + iz;
            float c000 = __ldg(p);
            float c001 = __ldg(p + 1);
            float c010 = __ldg(p + 256);
            float c011 = __ldg(p + 257);
            float c100 = __ldg(p + 65536);
            float c101 = __ldg(p + 65537);
            float c110 = __ldg(p + 65792);
            float c111 = __ldg(p + 65793);

            float c00 = fmaf(az, c001 - c000, c000);
            float c01 = fmaf(az, c011 - c010, c010);
            float c10 = fmaf(az, c101 - c100, c100);
            float c11 = fmaf(az, c111 - c110, c110);
            float c0  = fmaf(ay, c01 - c00, c00);
            float c1  = fmaf(ay, c11 - c10, c10);
            acc += fmaf(ax, c1 - c0, c0);
        }

        // --- Guarded tail: [B+1, s_hi] (at most ~1 iteration per lane) ---
        #pragma unroll 1
        for (int s = B + 1 + lane; s <= s_hi; s += 32) {
            float sf = (float)s;
            acc += trilinear_guarded(vol,
                                     fmaf(sf, ddx, p0x),
                                     fmaf(sf, ddy, p0y),
                                     fmaf(sf, ddz, p0z));
        }
    }

    // Warp reduction
    #pragma unroll
    for (int o = 16; o > 0; o >>= 1)
        acc += __shfl_down_sync(0xFFFFFFFFu, acc, o);

    if (lane == 0) out[gwarp] = acc * step;
}

extern "C" void kernel_launch(void* const* d_in, const int* in_sizes, int n_in,
                              void* d_out, int out_size) {
    const float* vol    = (const float*)d_in[0];
    const float* k_inv  = (const float*)d_in[1];
    const float* rt_inv = (const float*)d_in[2];
    const float* sdd    = (const float*)d_in[3];
    const float* aff    = (const float*)d_in[4];
    const int*   n_ptr  = (const int*)d_in[5];
    float* out = (float*)d_out;

    int n_warps = DRR_W * DRR_H;            // one warp per pixel
    int threads = 256;                      // 8 warps per block
    int blocks  = (n_warps * 32 + threads - 1) / threads;
    drr_kernel<<<blocks, threads>>>(vol, k_inv, rt_inv, sdd, aff, n_ptr, out);
}

// round 7
// speedup vs baseline: 1.9594x; 1.1430x over previous
#include <cuda_runtime.h>
#include <cuda_bf16.h>
#include <math.h>

// DRR raycast, two-phase:
//   Phase 1 (geom): 1 thread/pixel computes ray params + sample ranges -> scratch.
//   Phase 2 (main): 1 warp/pixel samples the volume, lanes stride sample axis.
// Inputs (metadata order): volume[256^3] f32, k_inv[1,3,3], rt_inv[1,4,4],
//                          sdd[1], affine_inv[4,4], n_samples int32
// Output: f32 [1,200,200]

#define DRR_W 200
#define DRR_H 200
#define DRR_VOL 256
#define NPIX (DRR_W * DRR_H)

// Scratch: per-pixel geometry. geomA = {p0x,p0y,p0z,step}, geomB = {ddx,ddy,ddz,0},
// rng = {s_lo, s_hi, A, B}.
__device__ float4 g_geomA[NPIX];
__device__ float4 g_geomB[NPIX];
__device__ int4   g_rng[NPIX];

__device__ __forceinline__ void axis_clip(float p, float d, float lo_b, float hi_b,
                                          float& lo, float& hi) {
    if (fabsf(d) < 1e-12f) {
        if (p < lo_b || p > hi_b) { lo = 1.0f; hi = 0.0f; }
    } else {
        float r  = 1.0f / d;
        float ta = (lo_b - p) * r;
        float tb = (hi_b - p) * r;
        lo = fmaxf(lo, fminf(ta, tb));
        hi = fminf(hi, fmaxf(ta, tb));
    }
}

// ---------------- Phase 1: geometry, one thread per pixel ----------------
__global__ void drr_geom_kernel(const float* __restrict__ k_inv,
                                const float* __restrict__ rt_inv,
                                const float* __restrict__ sdd_p,
                                const float* __restrict__ aff,
                                const int*   __restrict__ n_ptr) {
    int pix = blockIdx.x * blockDim.x + threadIdx.x;
    if (pix >= NPIX) return;

    int u = pix % DRR_W;
    int v = pix / DRR_W;

    int   n    = *n_ptr;
    float fn1  = (float)(n - 1);
    float invn = 1.0f / fn1;
    float sdd  = __ldg(sdd_p);
    float fu = (float)u, fv = (float)v;

    // tgt_cam = k_inv @ (u, v, 1) * sdd
    float tc0 = (__ldg(k_inv + 0) * fu + __ldg(k_inv + 1) * fv + __ldg(k_inv + 2)) * sdd;
    float tc1 = (__ldg(k_inv + 3) * fu + __ldg(k_inv + 4) * fv + __ldg(k_inv + 5)) * sdd;
    float tc2 = (__ldg(k_inv + 6) * fu + __ldg(k_inv + 7) * fv + __ldg(k_inv + 8)) * sdd;

    // ray = R @ tgt_cam ; src = t  (rt_inv is 4x4 row-major)
    float ray0 = __ldg(rt_inv + 0) * tc0 + __ldg(rt_inv + 1) * tc1 + __ldg(rt_inv + 2)  * tc2;
    float ray1 = __ldg(rt_inv + 4) * tc0 + __ldg(rt_inv + 5) * tc1 + __ldg(rt_inv + 6)  * tc2;
    float ray2 = __ldg(rt_inv + 8) * tc0 + __ldg(rt_inv + 9) * tc1 + __ldg(rt_inv + 10) * tc2;
    float sx = __ldg(rt_inv + 3), sy = __ldg(rt_inv + 7), sz = __ldg(rt_inv + 11);

    float step = sqrtf(ray0 * ray0 + ray1 * ray1 + ray2 * ray2) * invn;

    // vox(s) = p0 + ts * d   (affine_inv 4x4 row-major; only top 3 rows used)
    float p0x = __ldg(aff + 0) * sx + __ldg(aff + 1) * sy + __ldg(aff + 2)  * sz + __ldg(aff + 3);
    float p0y = __ldg(aff + 4) * sx + __ldg(aff + 5) * sy + __ldg(aff + 6)  * sz + __ldg(aff + 7);
    float p0z = __ldg(aff + 8) * sx + __ldg(aff + 9) * sy + __ldg(aff + 10) * sz + __ldg(aff + 11);
    float dx  = __ldg(aff + 0) * ray0 + __ldg(aff + 1) * ray1 + __ldg(aff + 2)  * ray2;
    float dy  = __ldg(aff + 4) * ray0 + __ldg(aff + 5) * ray1 + __ldg(aff + 6)  * ray2;
    float dz  = __ldg(aff + 8) * ray0 + __ldg(aff + 9) * ray1 + __ldg(aff + 10) * ray2;

    // Outer clip: any nonzero contribution requires coords in [-1, VOL].
    float lo = 0.0f, hi = 1.0f;
    axis_clip(p0x, dx, -1.0f, (float)DRR_VOL, lo, hi);
    axis_clip(p0y, dy, -1.0f, (float)DRR_VOL, lo, hi);
    axis_clip(p0z, dz, -1.0f, (float)DRR_VOL, lo, hi);

    // Interior clip: all 8 corners provably in-bounds when coords in [0, 254.99].
    float li = 0.0f, hii = 1.0f;
    axis_clip(p0x, dx, 0.0f, 254.99f, li, hii);
    axis_clip(p0y, dy, 0.0f, 254.99f, li, hii);
    axis_clip(p0z, dz, 0.0f, 254.99f, li, hii);

    int s_lo, s_hi, A, B;
    if (lo <= hi) {
        s_lo = (int)floorf(lo * fn1) - 2;
        s_hi = (int)ceilf(hi * fn1) + 2;
        if (s_lo < 0) s_lo = 0;
        if (s_hi > n - 1) s_hi = n - 1;

        if (li <= hii) {
            A = (int)ceilf(li * fn1) + 1;
            B = (int)floorf(hii * fn1) - 1;
            if (A < s_lo) A = s_lo;
            if (B > s_hi) B = s_hi;
            if (B < A) { A = s_hi + 1; B = s_hi; }   // empty interior
        } else {
            A = s_hi + 1; B = s_hi;                   // empty interior
        }
    } else {
        s_lo = 0; s_hi = -1; A = 1; B = 0;            // empty ray
    }

    g_geomA[pix] = make_float4(p0x, p0y, p0z, step);
    g_geomB[pix] = make_float4(dx * invn, dy * invn, dz * invn, 0.0f);
    g_rng[pix]   = make_int4(s_lo, s_hi, A, B);
}

// ---------------- Phase 2: sampling, one warp per pixel ----------------
__device__ __forceinline__ float fetch_vox(const float* __restrict__ vol,
                                           int x, int y, int z) {
    if ((unsigned)x < (unsigned)DRR_VOL &&
        (unsigned)y < (unsigned)DRR_VOL &&
        (unsigned)z < (unsigned)DRR_VOL) {
        return __ldg(vol + (x << 16) + (y << 8) + z);
    }
    return 0.0f;
}

__device__ __forceinline__ float trilinear_guarded(const float* __restrict__ vol,
                                                   float x, float y, float z) {
    float fx = floorf(x), fy = floorf(y), fz = floorf(z);
    int ix = (int)fx, iy = (int)fy, iz = (int)fz;
    float ax = x - fx, ay = y - fy, az = z - fz;

    float c000 = fetch_vox(vol, ix,     iy,     iz);
    float c001 = fetch_vox(vol, ix,     iy,     iz + 1);
    float c010 = fetch_vox(vol, ix,     iy + 1, iz);
    float c011 = fetch_vox(vol, ix,     iy + 1, iz + 1);
    float c100 = fetch_vox(vol, ix + 1, iy,     iz);
    float c101 = fetch_vox(vol, ix + 1, iy,     iz + 1);
    float c110 = fetch_vox(vol, ix + 1, iy + 1, iz);
    float c111 = fetch_vox(vol, ix + 1, iy + 1, iz + 1);

    float c00 = fmaf(az, c001 - c000, c000);
    float c01 = fmaf(az, c011 - c010, c010);
    float c10 = fmaf(az, c101 - c100, c100);
    float c11 = fmaf(az, c111 - c110, c110);
    float c0  = fmaf(ay, c01 - c00, c00);
    float c1  = fmaf(ay, c11 - c10, c10);
    return fmaf(ax, c1 - c0, c0);
}

__global__ __launch_bounds__(256, 6)
void drr_main_kernel(const float* __restrict__ vol,
                     float* __restrict__ out) {
    int gwarp = (blockIdx.x * blockDim.x + threadIdx.x) >> 5;
    int lane  = threadIdx.x & 31;
    if (gwarp >= NPIX) return;

    float4 ga = __ldg(&g_geomA[gwarp]);
    float4 gb = __ldg(&g_geomB[gwarp]);
    int4   rg = __ldg(&g_rng[gwarp]);

    float p0x = ga.x, p0y = ga.y, p0z = ga.z, step = ga.w;
    float ddx = gb.x, ddy = gb.y, ddz = gb.z;
    int s_lo = rg.x, s_hi = rg.y, A = rg.z, B = rg.w;

    float acc = 0.0f;

    // --- Guarded head: [s_lo, A-1] ---
    #pragma unroll 1
    for (int s = s_lo + lane; s <= A - 1; s += 32) {
        float sf = (float)s;
        acc += trilinear_guarded(vol,
                                 fmaf(sf, ddx, p0x),
                                 fmaf(sf, ddy, p0y),
                                 fmaf(sf, ddz, p0z));
    }

    // --- Unguarded interior bulk: [A, B] ---
    for (int s = A + lane; s <= B; s += 32) {
        float sf = (float)s;
        float x = fmaf(sf, ddx, p0x);
        float y = fmaf(sf, ddy, p0y);
        float z = fmaf(sf, ddz, p0z);
        int ix = __float2int_rd(x), iy = __float2int_rd(y), iz = __float2int_rd(z);
        float ax = x - (float)ix, ay = y - (float)iy, az = z - (float)iz;

        const float* p = vol + (ix << 16) + (iy << 8) + iz;
        float c000 = __ldg(p);
        float c001 = __ldg(p + 1);
        float c010 = __ldg(p + 256);
        float c011 = __ldg(p + 257);
        float c100 = __ldg(p + 65536);
        float c101 = __ldg(p + 65537);
        float c110 = __ldg(p + 65792);
        float c111 = __ldg(p + 65793);

        float c00 = fmaf(az, c001 - c000, c000);
        float c01 = fmaf(az, c011 - c010, c010);
        float c10 = fmaf(az, c101 - c100, c100);
        float c11 = fmaf(az, c111 - c110, c110);
        float c0  = fmaf(ay, c01 - c00, c00);
        float c1  = fmaf(ay, c11 - c10, c10);
        acc += fmaf(ax, c1 - c0, c0);
    }

    // --- Guarded tail: [B+1, s_hi] ---
    #pragma unroll 1
    for (int s = B + 1 + lane; s <= s_hi; s += 32) {
        float sf = (float)s;
        acc += trilinear_guarded(vol,
                                 fmaf(sf, ddx, p0x),
                                 fmaf(sf, ddy, p0y),
                                 fmaf(sf, ddz, p0z));
    }

    // Warp reduction
    #pragma unroll
    for (int o = 16; o > 0; o >>= 1)
        acc += __shfl_down_sync(0xFFFFFFFFu, acc, o);

    if (lane == 0) out[gwarp] = acc * step;
}

extern "C" void kernel_launch(void* const* d_in, const int* in_sizes, int n_in,
                              void* d_out, int out_size) {
    const float* vol    = (const float*)d_in[0];
    const float* k_inv  = (const float*)d_in[1];
    const float* rt_inv = (const float*)d_in[2];
    const float* sdd    = (const float*)d_in[3];
    const float* aff    = (const float*)d_in[4];
    const int*   n_ptr  = (const int*)d_in[5];
    float* out = (float*)d_out;

    // Phase 1: per-pixel geometry
    drr_geom_kernel<<<(NPIX + 255) / 256, 256>>>(k_inv, rt_inv, sdd, aff, n_ptr);

    // Phase 2: sampling, one warp per pixel
    int threads = 256;
    int blocks  = (NPIX * 32 + threads - 1) / threads;
    drr_main_kernel<<<blocks, threads>>>(vol, out);
}